// round 9
// baseline (speedup 1.0000x reference)
#include <cuda_runtime.h>

#define NEG 0.01f
#define BN_EPS 1e-5f
#define HDIM 64
#define MAXN 100000

// scratch (static __device__ allocation is allowed; no runtime allocs)
__device__ float g_x[(size_t)MAXN * HDIM];            // fused features   [N,64]
__device__ float g_agg[(size_t)2 * MAXN * HDIM];      // per-relation sums [2,N,64]
__device__ float g_cnt[(size_t)2 * MAXN];             // per-relation edge counts

__device__ __forceinline__ float leaky(float v) { return v > 0.f ? v : NEG * v; }

// ---------------------------------------------------------------------------
// zero scratch
// ---------------------------------------------------------------------------
__global__ void zero_kernel(int N) {
    int total4 = (2 * N * HDIM) / 4;
    float4* a4 = reinterpret_cast<float4*>(g_agg);
    for (int i = blockIdx.x * blockDim.x + threadIdx.x; i < total4;
         i += gridDim.x * blockDim.x)
        a4[i] = make_float4(0.f, 0.f, 0.f, 0.f);
    for (int i = blockIdx.x * blockDim.x + threadIdx.x; i < 2 * N;
         i += gridDim.x * blockDim.x)
        g_cnt[i] = 0.f;
}

// ---------------------------------------------------------------------------
// fused feature kernel: x = leaky(bn(des@Wd.T)) + leaky(bn(num@Wn.T)) + leaky(bn(cat@Wc.T))
// Tiled fp32 GEMM for the des branch (K=768), num/cat (K=5/6) in the epilogue.
// BM=128, BN=64(all), BK=32, 256 threads, thread tile 8x4.
// ---------------------------------------------------------------------------
__global__ __launch_bounds__(256) void fuse_kernel(
    const float* __restrict__ des, const float* __restrict__ num,
    const float* __restrict__ cat,
    const float* __restrict__ desW, const float* __restrict__ desb,
    const float* __restrict__ desg, const float* __restrict__ desbeta,
    const float* __restrict__ desm, const float* __restrict__ desv,
    const float* __restrict__ numW, const float* __restrict__ numb,
    const float* __restrict__ numg, const float* __restrict__ numbeta,
    const float* __restrict__ numm, const float* __restrict__ numv,
    const float* __restrict__ catW, const float* __restrict__ catb,
    const float* __restrict__ catg, const float* __restrict__ catbeta,
    const float* __restrict__ catm, const float* __restrict__ catv,
    int N)
{
    __shared__ float As[32][132];   // [k][m], padded: stores conflict-light, float4 reads aligned
    __shared__ float Bs[32][68];    // [k][n]
    __shared__ float sdes[64], cdes[64], snum[64], cnum[64], scat[64], ccat[64];
    __shared__ float numWs[64 * 5], catWs[64 * 6];

    const int tid = threadIdx.x;

    // fold BN into scale/offset per output channel: y = z*s + c, c = (b_lin - m)*s + beta
    if (tid < 64) {
        int j = tid;
        float s;
        s = desg[j] * rsqrtf(desv[j] + BN_EPS);
        sdes[j] = s; cdes[j] = (desb[j] - desm[j]) * s + desbeta[j];
        s = numg[j] * rsqrtf(numv[j] + BN_EPS);
        snum[j] = s; cnum[j] = (numb[j] - numm[j]) * s + numbeta[j];
        s = catg[j] * rsqrtf(catv[j] + BN_EPS);
        scat[j] = s; ccat[j] = (catb[j] - catm[j]) * s + catbeta[j];
    }
    for (int i = tid; i < 64 * 5; i += 256) numWs[i] = numW[i];
    for (int i = tid; i < 64 * 6; i += 256) catWs[i] = catW[i];

    const int m0 = blockIdx.x * 128;
    const int tx = tid & 15;        // col group: cols tx*4 .. tx*4+3
    const int ty = tid >> 4;        // row group: rows ty*8 .. ty*8+7

    float acc[8][4];
#pragma unroll
    for (int i = 0; i < 8; i++)
#pragma unroll
        for (int j = 0; j < 4; j++) acc[i][j] = 0.f;

    for (int kt = 0; kt < 768; kt += 32) {
        __syncthreads();
        // load A tile: 128 rows x 32 k
#pragma unroll
        for (int l = tid; l < 128 * 32; l += 256) {
            int m = l >> 5, k = l & 31;
            int row = m0 + m;
            As[k][m] = (row < N) ? des[(size_t)row * 768 + kt + k] : 0.f;
        }
        // load B tile: 64 out x 32 k  (desW is [64,768] row-major)
#pragma unroll
        for (int l = tid; l < 64 * 32; l += 256) {
            int n = l >> 5, k = l & 31;
            Bs[k][n] = desW[(size_t)n * 768 + kt + k];
        }
        __syncthreads();

#pragma unroll
        for (int kk = 0; kk < 32; kk++) {
            float4 a0 = *reinterpret_cast<const float4*>(&As[kk][ty * 8]);
            float4 a1 = *reinterpret_cast<const float4*>(&As[kk][ty * 8 + 4]);
            float4 b  = *reinterpret_cast<const float4*>(&Bs[kk][tx * 4]);
            float av[8] = {a0.x, a0.y, a0.z, a0.w, a1.x, a1.y, a1.z, a1.w};
            float bv[4] = {b.x, b.y, b.z, b.w};
#pragma unroll
            for (int i = 0; i < 8; i++)
#pragma unroll
                for (int j = 0; j < 4; j++) acc[i][j] += av[i] * bv[j];
        }
    }

    // epilogue: BN+leaky on des branch, plus num/cat branches
#pragma unroll
    for (int i = 0; i < 8; i++) {
        int m = m0 + ty * 8 + i;
        if (m >= N) continue;
        float nv[5], cv[6];
#pragma unroll
        for (int q = 0; q < 5; q++) nv[q] = num[(size_t)m * 5 + q];
#pragma unroll
        for (int q = 0; q < 6; q++) cv[q] = cat[(size_t)m * 6 + q];
        float4 o;
        float res[4];
#pragma unroll
        for (int j = 0; j < 4; j++) {
            int c = tx * 4 + j;
            float d = leaky(acc[i][j] * sdes[c] + cdes[c]);
            float zn = 0.f, zc = 0.f;
#pragma unroll
            for (int q = 0; q < 5; q++) zn += nv[q] * numWs[c * 5 + q];
#pragma unroll
            for (int q = 0; q < 6; q++) zc += cv[q] * catWs[c * 6 + q];
            float dn = leaky(zn * snum[c] + cnum[c]);
            float dc = leaky(zc * scat[c] + ccat[c]);
            res[j] = d + dn + dc;
        }
        o.x = res[0]; o.y = res[1]; o.z = res[2]; o.w = res[3];
        *reinterpret_cast<float4*>(&g_x[(size_t)m * HDIM + tx * 4]) = o;
    }
}

// ---------------------------------------------------------------------------
// edge kernel: per-relation scatter-add of raw x[src] into g_agg[r][dst]
// (relation linear commutes with the segment mean, applied later per node)
// 16 lanes per edge, float4 atomics (RED.128).
// ---------------------------------------------------------------------------
__global__ __launch_bounds__(256) void edge_kernel(
    const int* __restrict__ edge_index, const int* __restrict__ edge_type,
    int E, int N)
{
    int warp = (blockIdx.x * blockDim.x + threadIdx.x) >> 5;
    int lane = threadIdx.x & 31;
    int e = warp * 2 + (lane >> 4);
    if (e >= E) return;
    int sub = lane & 15;

    int src = edge_index[e];
    int dst = edge_index[E + e];
    int r   = edge_type[e];

    const float4* xrow = reinterpret_cast<const float4*>(g_x + (size_t)src * HDIM);
    float4 v = xrow[sub];
    float4* arow = reinterpret_cast<float4*>(g_agg + ((size_t)r * N + dst) * HDIM);
    atomicAdd(arow + sub, v);
    if (sub == 0) atomicAdd(&g_cnt[(size_t)r * N + dst], 1.0f);
}

// ---------------------------------------------------------------------------
// final kernel: per node
//   acc = sum_r (agg_r / max(cnt_r,1)) @ rgcnW[r].T ; x2 = leaky(acc/2)
//   h = leaky(x2 @ W1.T + b1) ; out = h @ W2.T + b2
// warp per node, 4 nodes per warp sequentially; smem-transposed weights.
// ---------------------------------------------------------------------------
__global__ __launch_bounds__(256) void final_kernel(
    const float* __restrict__ rgcnW,   // [2,64,64]
    const float* __restrict__ W1, const float* __restrict__ b1,  // [32,64],[32]
    const float* __restrict__ W2, const float* __restrict__ b2,  // [2,32],[2]
    float* __restrict__ out, int N)
{
    __shared__ float Wt[2 * 64 * 64];    // Wt[(r*64+k)*64 + j] = rgcnW[r][j][k]
    __shared__ float W1t[64 * 32];       // W1t[k*32 + j] = W1[j][k]
    __shared__ float W2s[64];            // [j*32 + k]
    __shared__ float b1s[32];
    __shared__ float b2s[2];
    __shared__ float ash[8][128];
    __shared__ float x2sh[8][64];

    const int tid = threadIdx.x;
    for (int i = tid; i < 8192; i += 256) {
        int r = i >> 12, rem = i & 4095, k = rem >> 6, j = rem & 63;
        Wt[i] = rgcnW[(size_t)r * 4096 + j * 64 + k];
    }
    for (int i = tid; i < 2048; i += 256) {
        int k = i >> 5, j = i & 31;
        W1t[i] = W1[(size_t)j * 64 + k];
    }
    if (tid < 64) W2s[tid] = W2[tid];
    if (tid < 32) b1s[tid] = b1[tid];
    if (tid < 2)  b2s[tid] = b2[tid];
    __syncthreads();

    const int w = tid >> 5;
    const int lane = tid & 31;
    const int base = blockIdx.x * 32 + w * 4;

    for (int it = 0; it < 4; it++) {
        int n = base + it;
        if (n >= N) break;

        float c0 = g_cnt[n];
        float c1 = g_cnt[(size_t)N + n];
        float s0 = 1.0f / fmaxf(c0, 1.0f);
        float s1 = 1.0f / fmaxf(c1, 1.0f);

        float2 v0 = reinterpret_cast<const float2*>(g_agg + (size_t)n * HDIM)[lane];
        float2 v1 = reinterpret_cast<const float2*>(g_agg + ((size_t)N + n) * HDIM)[lane];
        ash[w][2 * lane]      = v0.x * s0;
        ash[w][2 * lane + 1]  = v0.y * s0;
        ash[w][64 + 2 * lane]     = v1.x * s1;
        ash[w][64 + 2 * lane + 1] = v1.y * s1;
        __syncwarp();

        // GEMV over both relations: lane owns output cols {2*lane, 2*lane+1}
        float a0 = 0.f, a1 = 0.f;
#pragma unroll 8
        for (int k = 0; k < 128; k++) {
            int r = k >> 6, kk = k & 63;
            float a = ash[w][k];
            float2 ww = reinterpret_cast<const float2*>(&Wt[((r << 6) + kk) << 6])[lane];
            a0 += a * ww.x;
            a1 += a * ww.y;
        }
        float x0 = leaky(a0 * 0.5f);
        float x1 = leaky(a1 * 0.5f);
        reinterpret_cast<float2*>(x2sh[w])[lane] = make_float2(x0, x1);
        __syncwarp();

        // classifier layer 1: h[lane]
        float hv = b1s[lane];
#pragma unroll 8
        for (int k = 0; k < 64; k++) hv += x2sh[w][k] * W1t[k * 32 + lane];
        hv = leaky(hv);

        // layer 2: 2 outputs via warp reduction
        float o0 = hv * W2s[lane];
        float o1 = hv * W2s[32 + lane];
#pragma unroll
        for (int off = 16; off > 0; off >>= 1) {
            o0 += __shfl_xor_sync(0xffffffffu, o0, off);
            o1 += __shfl_xor_sync(0xffffffffu, o1, off);
        }
        if (lane == 0) {
            out[(size_t)n * 2]     = o0 + b2s[0];
            out[(size_t)n * 2 + 1] = o1 + b2s[1];
        }
        __syncwarp();
    }
}

// ---------------------------------------------------------------------------
// Input order follows setup_inputs() dict insertion order (= metadata.txt):
//  0 des, 1 num, 2 cat, 3 edge_index, 4 edge_type,
//  5 des_W, 6 des_b, 7 num_W, 8 num_b, 9 cat_W, 10 cat_b,
// 11 des_g, 12 des_beta, 13 des_m, 14 des_v,
// 15 num_g, 16 num_beta, 17 num_m, 18 num_v,
// 19 cat_g, 20 cat_beta, 21 cat_m, 22 cat_v,
// 23 rgcn_W, 24 cls_W1, 25 cls_b1, 26 cls_W2, 27 cls_b2
// ---------------------------------------------------------------------------
extern "C" void kernel_launch(void* const* d_in, const int* in_sizes, int n_in,
                              void* d_out, int out_size)
{
    const float* des  = (const float*)d_in[0];
    const float* num  = (const float*)d_in[1];
    const float* cat  = (const float*)d_in[2];
    const int*   ei   = (const int*)d_in[3];
    const int*   et   = (const int*)d_in[4];
    const float* desW = (const float*)d_in[5];
    const float* desb = (const float*)d_in[6];
    const float* numW = (const float*)d_in[7];
    const float* numb = (const float*)d_in[8];
    const float* catW = (const float*)d_in[9];
    const float* catb = (const float*)d_in[10];
    const float* desg = (const float*)d_in[11];
    const float* desbeta = (const float*)d_in[12];
    const float* desm = (const float*)d_in[13];
    const float* desv = (const float*)d_in[14];
    const float* numg = (const float*)d_in[15];
    const float* numbeta = (const float*)d_in[16];
    const float* numm = (const float*)d_in[17];
    const float* numv = (const float*)d_in[18];
    const float* catg = (const float*)d_in[19];
    const float* catbeta = (const float*)d_in[20];
    const float* catm = (const float*)d_in[21];
    const float* catv = (const float*)d_in[22];
    const float* rgcnW = (const float*)d_in[23];
    const float* W1 = (const float*)d_in[24];
    const float* b1 = (const float*)d_in[25];
    const float* W2 = (const float*)d_in[26];
    const float* b2 = (const float*)d_in[27];
    float* out = (float*)d_out;

    int N = in_sizes[0] / 768;
    int E = in_sizes[4];

    zero_kernel<<<1184, 256>>>(N);
    fuse_kernel<<<(N + 127) / 128, 256>>>(
        des, num, cat,
        desW, desb, desg, desbeta, desm, desv,
        numW, numb, numg, numbeta, numm, numv,
        catW, catb, catg, catbeta, catm, catv, N);
    edge_kernel<<<(E + 15) / 16, 256>>>(ei, et, E, N);
    final_kernel<<<(N + 31) / 32, 256>>>(rgcnW, W1, b1, W2, b2, out, N);
}